// round 11
// baseline (speedup 1.0000x reference)
#include <cuda_runtime.h>
#include <cuda_bf16.h>
#include <cstdint>
#include <cstring>

#define DI __device__ __forceinline__

// ---------------- static scratch (no allocation allowed) ----------------
__device__ __align__(16) uint8_t g_sW8[1966080];           // (g1*W1*64)^T e4m3 [512][C] per level
__device__ float g_proto_mean[4 * 2048];
__device__ float g_s2ss2[8];                               // per level: sum, sumsq of proto ctx
__device__ float g_gw[2048], g_bw[2048], g_u2[2048];
__device__ float g_text[4096];                             // l2-normalized text [8][512]
__device__ float g_logits[8192 * 32];                      // [B][4][8] pre-scale logits

__constant__ int cC[4]  = {256, 512, 1024, 2048};
__constant__ int cWO[4] = {0, 131072, 393216, 917504};     // byte offsets into g_sW8 (512*C)

// ---------------- PTX helpers ----------------
DI uint32_t su32(const void* p) {
    uint32_t a;
    asm("{ .reg .u64 t; cvta.to.shared.u64 t, %1; cvt.u32.u64 %0, t; }" : "=r"(a) : "l"(p));
    return a;
}
DI void cp16(uint32_t d, const void* s) {
    asm volatile("cp.async.cg.shared.global [%0], [%1], 16;" :: "r"(d), "l"(s));
}
DI void cpcommit() { asm volatile("cp.async.commit_group;"); }
DI void sts128(uint32_t a, uint32_t r0, uint32_t r1, uint32_t r2, uint32_t r3) {
    asm volatile("st.shared.v4.b32 [%0], {%1, %2, %3, %4};"
                 :: "r"(a), "r"(r0), "r"(r1), "r"(r2), "r"(r3) : "memory");
}
DI void ldmA(uint32_t* r, uint32_t a) {
    asm volatile("ldmatrix.sync.aligned.m8n8.x4.shared.b16 {%0,%1,%2,%3}, [%4];"
                 : "=r"(r[0]), "=r"(r[1]), "=r"(r[2]), "=r"(r[3]) : "r"(a));
}
// fp8 e4m3 mma: D(16x8 f32) += A(16x32 e4m3) x B(32x8 e4m3)
DI void mma16832(float* c, const uint32_t* a, uint32_t b0, uint32_t b1) {
    asm volatile(
        "mma.sync.aligned.m16n8k32.row.col.f32.e4m3.e4m3.f32 "
        "{%0,%1,%2,%3}, {%4,%5,%6,%7}, {%8,%9}, {%0,%1,%2,%3};"
        : "+f"(c[0]), "+f"(c[1]), "+f"(c[2]), "+f"(c[3])
        : "r"(a[0]), "r"(a[1]), "r"(a[2]), "r"(a[3]), "r"(b0), "r"(b1));
}
// pack 4 fp32 -> 4 e4m3 bytes (byte i = f_i)
DI uint32_t q4e4m3(float f0, float f1, float f2, float f3) {
    uint16_t lo, hi;
    asm("cvt.rn.satfinite.e4m3x2.f32 %0, %1, %2;" : "=h"(lo) : "f"(f1), "f"(f0));
    asm("cvt.rn.satfinite.e4m3x2.f32 %0, %1, %2;" : "=h"(hi) : "f"(f3), "f"(f2));
    return (uint32_t)lo | ((uint32_t)hi << 16);
}

static constexpr float WSCALE = 64.f;
static constexpr float INV_WSCALE = 1.f / 64.f;

// ---------------- precompute kernels ----------------
__global__ void k_zero(const float* b0, const float* b1, const float* b2, const float* b3) {
    const float* bs[4] = {b0, b1, b2, b3};
    const int lvl = blockIdx.x, d = threadIdx.x;
    g_gw[lvl * 512 + d] = 0.f;
    g_u2[lvl * 512 + d] = 0.f;
    g_bw[lvl * 512 + d] = bs[lvl][d];
    if (lvl == 0 && d < 8) g_s2ss2[d] = 0.f;
}

__global__ void k_proto(const float* __restrict__ p0, const float* __restrict__ p1,
                        const float* __restrict__ p2, const float* __restrict__ p3) {
    const float* pr[4] = {p0, p1, p2, p3};
    const int cb = blockIdx.x;
    const int lvl = cb < 1 ? 0 : cb < 3 ? 1 : cb < 7 ? 2 : 3;
    const int base4[4] = {0, 1, 3, 7};
    const int C = cC[lvl];
    const int c = (cb - base4[lvl]) * 256 + threadIdx.x;
    const float* P = pr[lvl];
    float s = 0.f;
    #pragma unroll 8
    for (int p = 0; p < 64; p++) s += P[p * C + c];
    const float pm = s * 0.015625f;
    g_proto_mean[lvl * 2048 + c] = pm;
    __shared__ float r1[256], r2[256];
    r1[threadIdx.x] = pm; r2[threadIdx.x] = pm * pm; __syncthreads();
    for (int o = 128; o; o >>= 1) {
        if (threadIdx.x < o) { r1[threadIdx.x] += r1[threadIdx.x + o]; r2[threadIdx.x] += r2[threadIdx.x + o]; }
        __syncthreads();
    }
    if (!threadIdx.x) {
        atomicAdd(&g_s2ss2[lvl * 2], r1[0]);
        atomicAdd(&g_s2ss2[lvl * 2 + 1], r2[0]);
    }
}

__global__ void k_text(const float* __restrict__ tb) {
    const int w = threadIdx.x >> 5, ln = threadIdx.x & 31;
    float4 v[4]; float ss = 0.f;
    #pragma unroll
    for (int j = 0; j < 4; j++) {
        v[j] = *(const float4*)(tb + w * 512 + ln * 4 + j * 128);
        ss += v[j].x * v[j].x + v[j].y * v[j].y + v[j].z * v[j].z + v[j].w * v[j].w;
    }
    #pragma unroll
    for (int o = 16; o; o >>= 1) ss += __shfl_xor_sync(~0u, ss, o);
    const float inv = 1.f / fmaxf(sqrtf(ss), 1e-12f);
    #pragma unroll
    for (int j = 0; j < 4; j++) {
        float4 u = v[j]; u.x *= inv; u.y *= inv; u.z *= inv; u.w *= inv;
        *(float4*)(g_text + w * 512 + ln * 4 + j * 128) = u;
    }
}

struct WPtr { const float* W[4]; const float* g[4]; const float* bb[4]; };

// 480 blocks x 512 threads; block = 16 j-rows, thread = 8 rows x 2 n-cols micro-tile.
// Emits TRANSPOSED fp8 W: g_sW8[n*C + j] = e4m3(g_j * W[j][n] * 64).
__global__ void k_wb(WPtr P) {
    __shared__ float red[256 * 6];
    const int cb = blockIdx.x;
    const int lvl = cb < 32 ? 0 : cb < 96 ? 1 : cb < 224 ? 2 : 3;
    const int base4[4] = {0, 32, 96, 224};
    const int j0 = (cb - base4[lvl]) * 16;
    const int C = cC[lvl];
    const int half = threadIdx.x >> 8;
    const int ci = threadIdx.x & 255;
    const int c0 = ci * 2;
    const int jb = j0 + half * 8;
    const float* W = P.W[lvl];
    const float* gg = P.g[lvl];
    const float* bv = P.bb[lvl];
    float gw0 = 0, gw1 = 0, bw0 = 0, bw1 = 0, u0 = 0, u1 = 0;
    float fa[8], fb[8];
    #pragma unroll
    for (int jj = 0; jj < 8; jj++) {
        const int j = jb + jj;
        const float gj = gg[j], bj = bv[j];
        const float2 w2 = *(const float2*)(W + (size_t)j * 512 + c0);
        gw0 = fmaf(gj, w2.x, gw0); gw1 = fmaf(gj, w2.y, gw1);
        bw0 = fmaf(bj, w2.x, bw0); bw1 = fmaf(bj, w2.y, bw1);
        if (j0 >= C) {
            const float pj = g_proto_mean[lvl * 2048 + (j - C)] * gj;
            u0 = fmaf(pj, w2.x, u0); u1 = fmaf(pj, w2.y, u1);
        } else {
            fa[jj] = gj * w2.x * WSCALE;
            fb[jj] = gj * w2.y * WSCALE;
        }
    }
    if (j0 < C) {
        uint2 pa, pb;
        pa.x = q4e4m3(fa[0], fa[1], fa[2], fa[3]);
        pa.y = q4e4m3(fa[4], fa[5], fa[6], fa[7]);
        pb.x = q4e4m3(fb[0], fb[1], fb[2], fb[3]);
        pb.y = q4e4m3(fb[4], fb[5], fb[6], fb[7]);
        *(uint2*)(g_sW8 + cWO[lvl] + (size_t)c0 * C + jb) = pa;
        *(uint2*)(g_sW8 + cWO[lvl] + (size_t)(c0 + 1) * C + jb) = pb;
    }
    if (half) {
        float* r = red + ci * 6;
        r[0] = gw0; r[1] = gw1; r[2] = bw0; r[3] = bw1; r[4] = u0; r[5] = u1;
    }
    __syncthreads();
    if (!half) {
        const float* r = red + ci * 6;
        gw0 += r[0]; gw1 += r[1]; bw0 += r[2]; bw1 += r[3]; u0 += r[4]; u1 += r[5];
        atomicAdd(&g_gw[lvl * 512 + c0], gw0);
        atomicAdd(&g_gw[lvl * 512 + c0 + 1], gw1);
        atomicAdd(&g_bw[lvl * 512 + c0], bw0);
        atomicAdd(&g_bw[lvl * 512 + c0 + 1], bw1);
        if (j0 >= C) {
            atomicAdd(&g_u2[lvl * 512 + c0], u0);
            atomicAdd(&g_u2[lvl * 512 + c0 + 1], u1);
        }
    }
}

// ---------------- main fused FP8 GEMM + epilogue ----------------
// CTA: 64 rows x 512 cols, BK=128 fp8 (128B rows), 16 warps (warp = 32-n slice).
// A: fp32 LDG -> regs -> e4m3 STS (fused convert + LN stats), 2 x 8KB buffers.
// B: fp8 K-major [n][C], 3-stage cp.async ring, 3 x 64KB. One barrier per chunk.
static constexpr int SM_B = 16384;
static constexpr int SM_TOTAL = 16384 + 3 * 65536;   // 212992 B

struct PPtr { const float* p[4]; };

__global__ void __launch_bounds__(512, 1) k_main(PPtr PA) {
    extern __shared__ char smem[];
    const uint32_t sb = su32(smem);
    const int tid = threadIdx.x, wid = tid >> 5, lane = tid & 31;
    const int lvl = 3 - (blockIdx.x >> 7);      // big levels first
    const int tile = blockIdx.x & 127;
    const int C = cC[lvl];
    const int nch = C >> 7;                     // 128 elems per chunk
    const int row0 = tile * 64;
    const float* Ag = PA.p[lvl] + (size_t)row0 * C;
    const uint8_t* Bg = g_sW8 + cWO[lvl];

    // A: thread t -> row t>>3, elems [(t&7)*16, +16) of each 128-wide chunk
    const int arow = tid >> 3, acol = (tid & 7) * 16;
    const float* aSrc = Ag + (size_t)arow * C + acol;
    const uint32_t aDst = sb + arow * 128 + (acol ^ ((arow & 7) << 4));

    float acc[4][4][4];
    #pragma unroll
    for (int i = 0; i < 4; i++)
        #pragma unroll
        for (int j = 0; j < 4; j++)
            #pragma unroll
            for (int k = 0; k < 4; k++) acc[i][j][k] = 0.f;

    const int rbase = (lane & 7) + 8 * ((lane >> 3) & 1);   // rows 0-15 pattern
    const int cbmat = (lane >> 4) * 16;                     // 16B half select
    const int xorv = (rbase & 7) << 4;
    const int cb = wid * 32;                                // warp n-slice base

    auto issueB = [&](int ch) {
        const int st = ch % 3;
        const uint8_t* bp = Bg + ch * 128;
        #pragma unroll
        for (int i = 0; i < 8; i++) {
            const int e = tid + 512 * i, r = e >> 3, c16 = e & 7;
            cp16(sb + SM_B + st * 65536 + r * 128 + ((c16 * 16) ^ ((r & 7) << 4)),
                 bp + (size_t)r * C + c16 * 16);
        }
        cpcommit();
    };

    float rs = 0.f, rq = 0.f;       // per-thread partial row stats
    float4 av[4];
    #pragma unroll
    for (int v = 0; v < 4; v++) av[v] = *(const float4*)(aSrc + v * 4);
    issueB(0);
    if (nch > 1) issueB(1);

    for (int ch = 0; ch < nch; ch++) {
        if (ch + 1 < nch) asm volatile("cp.async.wait_group 1;");
        else              asm volatile("cp.async.wait_group 0;");
        // convert + STS A(ch) from regs, accumulate stats
        {
            uint32_t q[4];
            #pragma unroll
            for (int v = 0; v < 4; v++) {
                const float4 a4 = av[v];
                rs += a4.x + a4.y + a4.z + a4.w;
                rq = fmaf(a4.x, a4.x, rq); rq = fmaf(a4.y, a4.y, rq);
                rq = fmaf(a4.z, a4.z, rq); rq = fmaf(a4.w, a4.w, rq);
                q[v] = q4e4m3(a4.x, a4.y, a4.z, a4.w);
            }
            sts128(aDst + (ch & 1) * 8192, q[0], q[1], q[2], q[3]);
        }
        __syncthreads();            // the only barrier per chunk
        if (ch + 2 < nch) issueB(ch + 2);
        if (ch + 1 < nch) {
            #pragma unroll
            for (int v = 0; v < 4; v++) av[v] = *(const float4*)(aSrc + (ch + 1) * 128 + v * 4);
        }
        const uint32_t sA = sb + (ch & 1) * 8192;
        const uint32_t sB = sb + SM_B + (ch % 3) * 65536;
        #pragma unroll
        for (int ks = 0; ks < 4; ks++) {
            uint32_t bf[2][4], af[4][4];
            #pragma unroll
            for (int np = 0; np < 2; np++)
                ldmA(bf[np], sB + (cb + np * 16 + rbase) * 128 + ((ks * 32 + cbmat) ^ xorv));
            #pragma unroll
            for (int mt = 0; mt < 4; mt++)
                ldmA(af[mt], sA + (mt * 16 + rbase) * 128 + ((ks * 32 + cbmat) ^ xorv));
            #pragma unroll
            for (int mt = 0; mt < 4; mt++)
                #pragma unroll
                for (int nt = 0; nt < 4; nt++)
                    mma16832(acc[mt][nt], af[mt],
                             bf[nt >> 1][nt & 1], bf[nt >> 1][(nt & 1) + 2]);
        }
    }
    __syncthreads();                // mainloop smem reads done before epilogue reuse

    // -------- epilogue (register-resident; reuses pipeline smem) --------
    float* sf   = (float*)smem;
    float* txs  = sf;                 // [8][512]
    float* u2s  = sf + 4096;
    float* gws  = u2s + 512;
    float* bws  = gws + 512;
    float2* srs = (float2*)(bws + 512);       // [64] (mean, inv)
    float2* sraw = srs + 64;                  // [64] raw (sum, sumsq)
    float* prp  = (float*)(sraw + 64);        // [64 rows][16 warps][9]
    float* rinv = prp + 64 * 16 * 9;          // [64]

    // reduce row stats across the 8 threads of each row
    #pragma unroll
    for (int o = 1; o < 8; o <<= 1) {
        rs += __shfl_xor_sync(~0u, rs, o);
        rq += __shfl_xor_sync(~0u, rq, o);
    }
    if ((tid & 7) == 0) sraw[arow] = make_float2(rs, rq);

    for (int i = tid; i < 4096; i += 512) txs[i] = g_text[i];
    if (tid < 512) {
        u2s[tid] = g_u2[lvl * 512 + tid];
        gws[tid] = g_gw[lvl * 512 + tid];
        bws[tid] = g_bw[lvl * 512 + tid];
    }
    __syncthreads();
    if (tid < 64) {
        const float s = sraw[tid].x + g_s2ss2[lvl * 2];
        const float q = sraw[tid].y + g_s2ss2[lvl * 2 + 1];
        const float invN = 1.f / (float)(2 * C);
        const float m = s * invN;
        const float var = q * invN - m * m;
        srs[tid] = make_float2(m, rsqrtf(var + 1e-5f));
    }
    __syncthreads();

    const int rr0 = lane >> 2;
    const int cq = (lane & 3) * 2;
    #pragma unroll
    for (int mt = 0; mt < 4; mt++) {
        const int r0 = mt * 16 + rr0, r1 = r0 + 8;
        const float2 s0 = srs[r0], s1 = srs[r1];
        const float ia0 = s0.y * INV_WSCALE, ia1 = s1.y * INV_WSCALE;  // fold 1/64 dequant
        float ss0 = 0.f, ss1 = 0.f;
        float dk0[8] = {0,0,0,0,0,0,0,0}, dk1[8] = {0,0,0,0,0,0,0,0};
        #pragma unroll
        for (int nt = 0; nt < 4; nt++) {
            const int c = cb + nt * 8 + cq;
            const float u2a = u2s[c], u2b = u2s[c + 1];
            const float gwa = gws[c], gwb = gws[c + 1];
            const float bwa = bws[c], bwb = bws[c + 1];
            const float h0 = fmaxf(ia0 * acc[mt][nt][0] + s0.y * (u2a - s0.x * gwa) + bwa, 0.f);
            const float h1 = fmaxf(ia0 * acc[mt][nt][1] + s0.y * (u2b - s0.x * gwb) + bwb, 0.f);
            const float h2 = fmaxf(ia1 * acc[mt][nt][2] + s1.y * (u2a - s1.x * gwa) + bwa, 0.f);
            const float h3 = fmaxf(ia1 * acc[mt][nt][3] + s1.y * (u2b - s1.x * gwb) + bwb, 0.f);
            ss0 = fmaf(h0, h0, ss0); ss0 = fmaf(h1, h1, ss0);
            ss1 = fmaf(h2, h2, ss1); ss1 = fmaf(h3, h3, ss1);
            #pragma unroll
            for (int k = 0; k < 8; k++) {
                const float2 t2 = *(const float2*)(txs + k * 512 + c);
                dk0[k] = fmaf(h0, t2.x, dk0[k]); dk0[k] = fmaf(h1, t2.y, dk0[k]);
                dk1[k] = fmaf(h2, t2.x, dk1[k]); dk1[k] = fmaf(h3, t2.y, dk1[k]);
            }
        }
        #pragma unroll
        for (int o = 1; o < 4; o <<= 1) {
            ss0 += __shfl_xor_sync(~0u, ss0, o);
            ss1 += __shfl_xor_sync(~0u, ss1, o);
            #pragma unroll
            for (int k = 0; k < 8; k++) {
                dk0[k] += __shfl_xor_sync(~0u, dk0[k], o);
                dk1[k] += __shfl_xor_sync(~0u, dk1[k], o);
            }
        }
        if ((lane & 3) == 0) {
            float* p0 = prp + (r0 * 16 + wid) * 9;
            float* p1 = prp + (r1 * 16 + wid) * 9;
            p0[0] = ss0; p1[0] = ss1;
            #pragma unroll
            for (int k = 0; k < 8; k++) { p0[1 + k] = dk0[k]; p1[1 + k] = dk1[k]; }
        }
    }
    __syncthreads();
    if (tid < 64) {
        float ss = 0.f;
        #pragma unroll
        for (int w = 0; w < 16; w++) ss += prp[(tid * 16 + w) * 9];
        rinv[tid] = 1.f / fmaxf(sqrtf(ss), 1e-12f);
    }
    __syncthreads();
    {
        const int row = tid >> 3, k = tid & 7;
        float d = 0.f;
        #pragma unroll
        for (int w = 0; w < 16; w++) d += prp[(row * 16 + w) * 9 + 1 + k];
        g_logits[(size_t)(row0 + row) * 32 + lvl * 8 + k] = d * rinv[row];
    }
}

// ---------------- final softmax over L ----------------
__global__ void k_fin(const float* __restrict__ ls, float* __restrict__ out) {
    const int i = blockIdx.x * 256 + threadIdx.x;  // b*8 + k
    const float s = fmaxf(ls[0], 1e-4f) * 0.044194173824159216f;  // clip * 1/sqrt(512)
    const int b = i >> 3, k = i & 7;
    float z[4], mx = -1e30f;
    #pragma unroll
    for (int l = 0; l < 4; l++) {
        z[l] = g_logits[b * 32 + l * 8 + k] * s;
        mx = fmaxf(mx, z[l]);
    }
    float e[4], sum = 0.f;
    #pragma unroll
    for (int l = 0; l < 4; l++) { e[l] = expf(z[l] - mx); sum += e[l]; }
    const float inv = 1.f / sum;
    #pragma unroll
    for (int l = 0; l < 4; l++) out[i * 4 + l] = e[l] * inv;
}

// ---------------- launch ----------------
extern "C" void kernel_launch(void* const* d_in, const int* in_sizes, int n_in,
                              void* d_out, int out_size) {
    const float *pooled[4], *proto[4], *lng[4], *lnb[4], *W[4], *bias[4];
    const bool interleaved = (in_sizes[1] == 16384);  // proto_0 = 64*256
    for (int i = 0; i < 4; i++) {
        if (interleaved) {
            pooled[i] = (const float*)d_in[6 * i + 0];
            proto[i]  = (const float*)d_in[6 * i + 1];
            lng[i]    = (const float*)d_in[6 * i + 2];
            lnb[i]    = (const float*)d_in[6 * i + 3];
            W[i]      = (const float*)d_in[6 * i + 4];
            bias[i]   = (const float*)d_in[6 * i + 5];
        } else {
            pooled[i] = (const float*)d_in[i];
            proto[i]  = (const float*)d_in[4 + i];
            lng[i]    = (const float*)d_in[8 + i];
            lnb[i]    = (const float*)d_in[12 + i];
            W[i]      = (const float*)d_in[16 + i];
            bias[i]   = (const float*)d_in[20 + i];
        }
    }
    const float* text = (const float*)d_in[24];
    const float* ls   = (const float*)d_in[25];

    k_zero<<<4, 512>>>(bias[0], bias[1], bias[2], bias[3]);
    k_proto<<<15, 256>>>(proto[0], proto[1], proto[2], proto[3]);
    k_text<<<1, 256>>>(text);
    WPtr wp;
    for (int i = 0; i < 4; i++) { wp.W[i] = W[i]; wp.g[i] = lng[i]; wp.bb[i] = lnb[i]; }
    k_wb<<<480, 512>>>(wp);

    PPtr pa;
    for (int i = 0; i < 4; i++) pa.p[i] = pooled[i];
    cudaFuncSetAttribute(k_main, cudaFuncAttributeMaxDynamicSharedMemorySize, SM_TOTAL);
    k_main<<<512, 512, SM_TOTAL>>>(pa);
    k_fin<<<256, 256>>>(ls, (float*)d_out);
}

// round 12
// speedup vs baseline: 1.0976x; 1.0976x over previous
#include <cuda_runtime.h>
#include <cuda_bf16.h>
#include <cstdint>
#include <cstring>

#define DI __device__ __forceinline__

// ---------------- static scratch (no allocation allowed) ----------------
__device__ __align__(16) __nv_bfloat16 g_sW[1966080];      // g1*W1 bf16 [C][512] per level
__device__ float g_proto_mean[4 * 2048];
__device__ float g_s2ss2[8];                               // per level: sum, sumsq of proto ctx
__device__ float g_gw[2048], g_bw[2048], g_u2[2048];
__device__ float g_text[4096];                             // l2-normalized text [8][512]
__device__ float g_logits[8192 * 32];                      // [B][4][8] pre-scale logits

__constant__ int cC[4]  = {256, 512, 1024, 2048};
__constant__ int cWO[4] = {0, 131072, 393216, 917504};     // elem offsets into g_sW

// ---------------- PTX helpers ----------------
DI uint32_t su32(const void* p) {
    uint32_t a;
    asm("{ .reg .u64 t; cvta.to.shared.u64 t, %1; cvt.u32.u64 %0, t; }" : "=r"(a) : "l"(p));
    return a;
}
DI void cp16(uint32_t d, const void* s) {
    asm volatile("cp.async.cg.shared.global [%0], [%1], 16;" :: "r"(d), "l"(s));
}
DI void cpcommit() { asm volatile("cp.async.commit_group;"); }
DI void sts64(uint32_t a, uint32_t lo, uint32_t hi) {
    asm volatile("st.shared.v2.b32 [%0], {%1, %2};" :: "r"(a), "r"(lo), "r"(hi) : "memory");
}
DI void ldmA(uint32_t* r, uint32_t a) {
    asm volatile("ldmatrix.sync.aligned.m8n8.x4.shared.b16 {%0,%1,%2,%3}, [%4];"
                 : "=r"(r[0]), "=r"(r[1]), "=r"(r[2]), "=r"(r[3]) : "r"(a));
}
DI void ldmBT(uint32_t* r, uint32_t a) {
    asm volatile("ldmatrix.sync.aligned.m8n8.x4.trans.shared.b16 {%0,%1,%2,%3}, [%4];"
                 : "=r"(r[0]), "=r"(r[1]), "=r"(r[2]), "=r"(r[3]) : "r"(a));
}
DI void mma16816(float* c, const uint32_t* a, const uint32_t* b) {
    asm volatile(
        "mma.sync.aligned.m16n8k16.row.col.f32.bf16.bf16.f32 "
        "{%0,%1,%2,%3}, {%4,%5,%6,%7}, {%8,%9}, {%0,%1,%2,%3};"
        : "+f"(c[0]), "+f"(c[1]), "+f"(c[2]), "+f"(c[3])
        : "r"(a[0]), "r"(a[1]), "r"(a[2]), "r"(a[3]), "r"(b[0]), "r"(b[1]));
}

// ---------------- fused precompute: proto mean + text l2norm + accum zero ----------------
struct PrePtr {
    const float* proto[4];
    const float* bias[4];
    const float* text;
};

__global__ void k_pre(PrePtr P) {
    const int bx = blockIdx.x;
    if (bx < 15) {
        // proto column means + level sum/sumsq
        const int lvl = bx < 1 ? 0 : bx < 3 ? 1 : bx < 7 ? 2 : 3;
        const int base4[4] = {0, 1, 3, 7};
        const int C = cC[lvl];
        const int c = (bx - base4[lvl]) * 256 + threadIdx.x;
        const float* Pp = P.proto[lvl];
        float s = 0.f;
        #pragma unroll 8
        for (int p = 0; p < 64; p++) s += Pp[p * C + c];
        const float pm = s * 0.015625f;
        g_proto_mean[lvl * 2048 + c] = pm;
        __shared__ float r1[256], r2[256];
        r1[threadIdx.x] = pm; r2[threadIdx.x] = pm * pm; __syncthreads();
        for (int o = 128; o; o >>= 1) {
            if (threadIdx.x < o) { r1[threadIdx.x] += r1[threadIdx.x + o]; r2[threadIdx.x] += r2[threadIdx.x + o]; }
            __syncthreads();
        }
        if (!threadIdx.x) {
            atomicAdd(&g_s2ss2[lvl * 2], r1[0]);
            atomicAdd(&g_s2ss2[lvl * 2 + 1], r2[0]);
        }
    } else if (bx == 15) {
        // text l2 normalize (8 warps, one per row)
        const int w = threadIdx.x >> 5, ln = threadIdx.x & 31;
        float4 v[4]; float ss = 0.f;
        #pragma unroll
        for (int j = 0; j < 4; j++) {
            v[j] = *(const float4*)(P.text + w * 512 + ln * 4 + j * 128);
            ss += v[j].x * v[j].x + v[j].y * v[j].y + v[j].z * v[j].z + v[j].w * v[j].w;
        }
        #pragma unroll
        for (int o = 16; o; o >>= 1) ss += __shfl_xor_sync(~0u, ss, o);
        const float inv = 1.f / fmaxf(sqrtf(ss), 1e-12f);
        #pragma unroll
        for (int j = 0; j < 4; j++) {
            float4 u = v[j]; u.x *= inv; u.y *= inv; u.z *= inv; u.w *= inv;
            *(float4*)(g_text + w * 512 + ln * 4 + j * 128) = u;
        }
    } else {
        // zero accumulators + seed bw with bias
        const int lvl = bx - 16;
        #pragma unroll
        for (int i = 0; i < 2; i++) {
            const int d = threadIdx.x + i * 256;
            g_gw[lvl * 512 + d] = 0.f;
            g_u2[lvl * 512 + d] = 0.f;
            g_bw[lvl * 512 + d] = P.bias[lvl][d];
        }
        if (lvl == 0 && threadIdx.x < 8) g_s2ss2[threadIdx.x] = 0.f;
    }
}

struct WPtr { const float* W[4]; const float* g[4]; const float* bb[4]; };

// 480 blocks x 512 threads; block = 16 j-rows, thread = 4 rows x 4 cols (float4 loads).
// 4 row-groups per block; smem cross-group reduce then one atomicAdd per col per block.
__global__ void k_wb(WPtr P) {
    __shared__ float red[3 * 128 * 12];     // groups 1..3, 128 ci, 12 floats
    const int cb = blockIdx.x;
    const int lvl = cb < 32 ? 0 : cb < 96 ? 1 : cb < 224 ? 2 : 3;
    const int base4[4] = {0, 32, 96, 224};
    const int j0 = (cb - base4[lvl]) * 16;
    const int C = cC[lvl];
    const int grp = threadIdx.x >> 7;       // 0..3 -> rows jb..jb+3
    const int ci = threadIdx.x & 127;
    const int c0 = ci * 4;
    const int jb = j0 + grp * 4;
    const float* W = P.W[lvl];
    const float* gg = P.g[lvl];
    const float* bv = P.bb[lvl];
    float gw[4] = {0, 0, 0, 0}, bw[4] = {0, 0, 0, 0}, uu[4] = {0, 0, 0, 0};
    uint2 outw[4];
    #pragma unroll
    for (int jj = 0; jj < 4; jj++) {
        const int j = jb + jj;
        const float gj = gg[j], bj = bv[j];
        const float4 w4 = *(const float4*)(W + (size_t)j * 512 + c0);
        gw[0] = fmaf(gj, w4.x, gw[0]); gw[1] = fmaf(gj, w4.y, gw[1]);
        gw[2] = fmaf(gj, w4.z, gw[2]); gw[3] = fmaf(gj, w4.w, gw[3]);
        bw[0] = fmaf(bj, w4.x, bw[0]); bw[1] = fmaf(bj, w4.y, bw[1]);
        bw[2] = fmaf(bj, w4.z, bw[2]); bw[3] = fmaf(bj, w4.w, bw[3]);
        if (j0 >= C) {
            const float pj = g_proto_mean[lvl * 2048 + (j - C)] * gj;
            uu[0] = fmaf(pj, w4.x, uu[0]); uu[1] = fmaf(pj, w4.y, uu[1]);
            uu[2] = fmaf(pj, w4.z, uu[2]); uu[3] = fmaf(pj, w4.w, uu[3]);
        } else {
            __nv_bfloat162 h0 = __floats2bfloat162_rn(gj * w4.x, gj * w4.y);
            __nv_bfloat162 h1 = __floats2bfloat162_rn(gj * w4.z, gj * w4.w);
            memcpy(&outw[jj].x, &h0, 4);
            memcpy(&outw[jj].y, &h1, 4);
        }
    }
    if (j0 < C) {
        #pragma unroll
        for (int jj = 0; jj < 4; jj++)
            *(uint2*)(g_sW + cWO[lvl] + (size_t)(jb + jj) * 512 + c0) = outw[jj];
    }
    if (grp) {
        float* r = red + ((grp - 1) * 128 + ci) * 12;
        #pragma unroll
        for (int c = 0; c < 4; c++) { r[c] = gw[c]; r[4 + c] = bw[c]; r[8 + c] = uu[c]; }
    }
    __syncthreads();
    if (!grp) {
        #pragma unroll
        for (int g2 = 0; g2 < 3; g2++) {
            const float* r = red + (g2 * 128 + ci) * 12;
            #pragma unroll
            for (int c = 0; c < 4; c++) { gw[c] += r[c]; bw[c] += r[4 + c]; uu[c] += r[8 + c]; }
        }
        #pragma unroll
        for (int c = 0; c < 4; c++) {
            atomicAdd(&g_gw[lvl * 512 + c0 + c], gw[c]);
            atomicAdd(&g_bw[lvl * 512 + c0 + c], bw[c]);
        }
        if (j0 >= C) {
            #pragma unroll
            for (int c = 0; c < 4; c++) atomicAdd(&g_u2[lvl * 512 + c0 + c], uu[c]);
        }
    }
}

// ---------------- main fused GEMM + epilogue (R9 proven version) ----------------
// CTA: 64 rows x 512 cols, BK=32, 16 warps (warp = 32-col slice).
// A: fp32 LDG -> regs -> bf16 STS (fused convert + LN stats), 2 x 8KB buffers.
// B: 4-stage cp.async ring, 4 x 32KB. ONE __syncthreads per K-chunk.
static constexpr int SM_B = 16384;
static constexpr int SM_TOTAL = 16384 + 4 * 32768;   // 147456 B

struct PPtr { const float* p[4]; };

__global__ void __launch_bounds__(512, 1) k_main(PPtr PA) {
    extern __shared__ char smem[];
    const uint32_t sb = su32(smem);
    const int tid = threadIdx.x, wid = tid >> 5, lane = tid & 31;
    const int lvl = 3 - (blockIdx.x >> 7);      // big levels first
    const int tile = blockIdx.x & 127;
    const int C = cC[lvl];
    const int nch = C >> 5;
    const int row0 = tile * 64;
    const float* Ag = PA.p[lvl] + (size_t)row0 * C;
    const __nv_bfloat16* Bg = g_sW + cWO[lvl];

    // A: thread t -> row t>>3, floats [(t&7)*4, +4) of each 32-wide chunk
    const int arow = tid >> 3, acol = (tid & 7) * 4;
    const float* aSrc = Ag + (size_t)arow * C + acol;
    const uint32_t aDst = sb + arow * 128 + ((acol * 2) ^ ((arow & 7) << 4));

    float acc[4][4][4];
    #pragma unroll
    for (int i = 0; i < 4; i++)
        #pragma unroll
        for (int j = 0; j < 4; j++)
            #pragma unroll
            for (int k = 0; k < 4; k++) acc[i][j][k] = 0.f;

    const int rbase = (lane & 7) + 8 * ((lane >> 3) & 1);
    const int cbmat = (lane >> 4) * 16;
    const int xorv = (rbase & 7) << 4;
    const int cb = wid * 32;

    auto issueB = [&](int ch) {
        const int st = ch & 3;
        const __nv_bfloat16* bp = Bg + (size_t)(ch * 32) * 512;
        #pragma unroll
        for (int i = 0; i < 4; i++) {
            const int c = tid + 512 * i, r = c >> 6, c16 = c & 63;
            cp16(sb + SM_B + st * 32768 + r * 1024 + ((c16 * 16) ^ ((r & 7) << 4)),
                 bp + r * 512 + c16 * 8);
        }
        cpcommit();
    };

    float rs = 0.f, rq = 0.f;       // per-thread partial row stats
    float4 av = *(const float4*)(aSrc);
    issueB(0);
    if (nch > 1) issueB(1);
    if (nch > 2) issueB(2);

    for (int ch = 0; ch < nch; ch++) {
        if (ch + 2 < nch)      asm volatile("cp.async.wait_group 2;");
        else if (ch + 1 < nch) asm volatile("cp.async.wait_group 1;");
        else                   asm volatile("cp.async.wait_group 0;");
        // convert + STS A(ch) from regs, accumulate stats
        {
            rs += av.x + av.y + av.z + av.w;
            rq = fmaf(av.x, av.x, rq); rq = fmaf(av.y, av.y, rq);
            rq = fmaf(av.z, av.z, rq); rq = fmaf(av.w, av.w, rq);
            __nv_bfloat162 h0 = __floats2bfloat162_rn(av.x, av.y);
            __nv_bfloat162 h1 = __floats2bfloat162_rn(av.z, av.w);
            uint32_t lo, hi; memcpy(&lo, &h0, 4); memcpy(&hi, &h1, 4);
            sts64(aDst + (ch & 1) * 8192, lo, hi);
        }
        __syncthreads();            // the ONLY barrier per chunk
        if (ch + 3 < nch) issueB(ch + 3);
        if (ch + 1 < nch) av = *(const float4*)(aSrc + (ch + 1) * 32);
        const uint32_t sA = sb + (ch & 1) * 8192;
        const uint32_t sB = sb + SM_B + (ch & 3) * 32768;
        #pragma unroll
        for (int ks = 0; ks < 2; ks++) {
            uint32_t bf[2][4], af[4][4];
            #pragma unroll
            for (int np = 0; np < 2; np++)
                ldmBT(bf[np], sB + (ks * 16 + rbase) * 1024 +
                              ((((cb + np * 16) * 2) + cbmat) ^ xorv));
            #pragma unroll
            for (int mt = 0; mt < 4; mt++)
                ldmA(af[mt], sA + (mt * 16 + rbase) * 128 + (((ks * 16) * 2 + cbmat) ^ xorv));
            #pragma unroll
            for (int mt = 0; mt < 4; mt++)
                #pragma unroll
                for (int nt = 0; nt < 4; nt++)
                    mma16816(acc[mt][nt], af[mt], &bf[nt >> 1][(nt & 1) * 2]);
        }
    }
    __syncthreads();                // mainloop smem reads done before epilogue reuse

    // -------- epilogue (register-resident; reuses pipeline smem) --------
    float* sf   = (float*)smem;
    float* txs  = sf;                 // [8][512]
    float* u2s  = sf + 4096;
    float* gws  = u2s + 512;
    float* bws  = gws + 512;
    float2* srs = (float2*)(bws + 512);       // [64] (mean, inv)
    float2* sraw = srs + 64;                  // [64] raw (sum, sumsq)
    float* prp  = (float*)(sraw + 64);        // [64 rows][16 warps][9]
    float* rinv = prp + 64 * 16 * 9;          // [64]

    // reduce row stats across the 8 threads of each row (lanes differ in bits 0-2)
    #pragma unroll
    for (int o = 1; o < 8; o <<= 1) {
        rs += __shfl_xor_sync(~0u, rs, o);
        rq += __shfl_xor_sync(~0u, rq, o);
    }
    if ((tid & 7) == 0) sraw[arow] = make_float2(rs, rq);

    for (int i = tid; i < 4096; i += 512) txs[i] = g_text[i];
    if (tid < 512) {
        u2s[tid] = g_u2[lvl * 512 + tid];
        gws[tid] = g_gw[lvl * 512 + tid];
        bws[tid] = g_bw[lvl * 512 + tid];
    }
    __syncthreads();
    if (tid < 64) {
        const float s = sraw[tid].x + g_s2ss2[lvl * 2];
        const float q = sraw[tid].y + g_s2ss2[lvl * 2 + 1];
        const float invN = 1.f / (float)(2 * C);
        const float m = s * invN;
        const float var = q * invN - m * m;
        srs[tid] = make_float2(m, rsqrtf(var + 1e-5f));
    }
    __syncthreads();

    const int rr0 = lane >> 2;
    const int cq = (lane & 3) * 2;
    #pragma unroll
    for (int mt = 0; mt < 4; mt++) {
        const int r0 = mt * 16 + rr0, r1 = r0 + 8;
        const float2 s0 = srs[r0], s1 = srs[r1];
        float ss0 = 0.f, ss1 = 0.f;
        float dk0[8] = {0,0,0,0,0,0,0,0}, dk1[8] = {0,0,0,0,0,0,0,0};
        #pragma unroll
        for (int nt = 0; nt < 4; nt++) {
            const int c = cb + nt * 8 + cq;
            const float u2a = u2s[c], u2b = u2s[c + 1];
            const float gwa = gws[c], gwb = gws[c + 1];
            const float bwa = bws[c], bwb = bws[c + 1];
            const float h0 = fmaxf(s0.y * (acc[mt][nt][0] + u2a - s0.x * gwa) + bwa, 0.f);
            const float h1 = fmaxf(s0.y * (acc[mt][nt][1] + u2b - s0.x * gwb) + bwb, 0.f);
            const float h2 = fmaxf(s1.y * (acc[mt][nt][2] + u2a - s1.x * gwa) + bwa, 0.f);
            const float h3 = fmaxf(s1.y * (acc[mt][nt][3] + u2b - s1.x * gwb) + bwb, 0.f);
            ss0 = fmaf(h0, h0, ss0); ss0 = fmaf(h1, h1, ss0);
            ss1 = fmaf(h2, h2, ss1); ss1 = fmaf(h3, h3, ss1);
            #pragma unroll
            for (int k = 0; k < 8; k++) {
                const float2 t2 = *(const float2*)(txs + k * 512 + c);
                dk0[k] = fmaf(h0, t2.x, dk0[k]); dk0[k] = fmaf(h1, t2.y, dk0[k]);
                dk1[k] = fmaf(h2, t2.x, dk1[k]); dk1[k] = fmaf(h3, t2.y, dk1[k]);
            }
        }
        #pragma unroll
        for (int o = 1; o < 4; o <<= 1) {
            ss0 += __shfl_xor_sync(~0u, ss0, o);
            ss1 += __shfl_xor_sync(~0u, ss1, o);
            #pragma unroll
            for (int k = 0; k < 8; k++) {
                dk0[k] += __shfl_xor_sync(~0u, dk0[k], o);
                dk1[k] += __shfl_xor_sync(~0u, dk1[k], o);
            }
        }
        if ((lane & 3) == 0) {
            float* p0 = prp + (r0 * 16 + wid) * 9;
            float* p1 = prp + (r1 * 16 + wid) * 9;
            p0[0] = ss0; p1[0] = ss1;
            #pragma unroll
            for (int k = 0; k < 8; k++) { p0[1 + k] = dk0[k]; p1[1 + k] = dk1[k]; }
        }
    }
    __syncthreads();
    if (tid < 64) {
        float ss = 0.f;
        #pragma unroll
        for (int w = 0; w < 16; w++) ss += prp[(tid * 16 + w) * 9];
        rinv[tid] = 1.f / fmaxf(sqrtf(ss), 1e-12f);
    }
    __syncthreads();
    {
        const int row = tid >> 3, k = tid & 7;
        float d = 0.f;
        #pragma unroll
        for (int w = 0; w < 16; w++) d += prp[(row * 16 + w) * 9 + 1 + k];
        g_logits[(size_t)(row0 + row) * 32 + lvl * 8 + k] = d * rinv[row];
    }
}

// ---------------- final softmax over L ----------------
__global__ void k_fin(const float* __restrict__ ls, float* __restrict__ out) {
    const int i = blockIdx.x * 256 + threadIdx.x;  // b*8 + k
    const float s = fmaxf(ls[0], 1e-4f) * 0.044194173824159216f;  // clip * 1/sqrt(512)
    const int b = i >> 3, k = i & 7;
    float z[4], mx = -1e30f;
    #pragma unroll
    for (int l = 0; l < 4; l++) {
        z[l] = g_logits[b * 32 + l * 8 + k] * s;
        mx = fmaxf(mx, z[l]);
    }
    float e[4], sum = 0.f;
    #pragma unroll
    for (int l = 0; l < 4; l++) { e[l] = expf(z[l] - mx); sum += e[l]; }
    const float inv = 1.f / sum;
    #pragma unroll
    for (int l = 0; l < 4; l++) out[i * 4 + l] = e[l] * inv;
}

// ---------------- launch ----------------
extern "C" void kernel_launch(void* const* d_in, const int* in_sizes, int n_in,
                              void* d_out, int out_size) {
    const float *pooled[4], *proto[4], *lng[4], *lnb[4], *W[4], *bias[4];
    const bool interleaved = (in_sizes[1] == 16384);  // proto_0 = 64*256
    for (int i = 0; i < 4; i++) {
        if (interleaved) {
            pooled[i] = (const float*)d_in[6 * i + 0];
            proto[i]  = (const float*)d_in[6 * i + 1];
            lng[i]    = (const float*)d_in[6 * i + 2];
            lnb[i]    = (const float*)d_in[6 * i + 3];
            W[i]      = (const float*)d_in[6 * i + 4];
            bias[i]   = (const float*)d_in[6 * i + 5];
        } else {
            pooled[i] = (const float*)d_in[i];
            proto[i]  = (const float*)d_in[4 + i];
            lng[i]    = (const float*)d_in[8 + i];
            lnb[i]    = (const float*)d_in[12 + i];
            W[i]      = (const float*)d_in[16 + i];
            bias[i]   = (const float*)d_in[20 + i];
        }
    }
    const float* text = (const float*)d_in[24];
    const float* ls   = (const float*)d_in[25];

    PrePtr pr;
    for (int i = 0; i < 4; i++) { pr.proto[i] = proto[i]; pr.bias[i] = bias[i]; }
    pr.text = text;
    k_pre<<<20, 256>>>(pr);

    WPtr wp;
    for (int i = 0; i < 4; i++) { wp.W[i] = W[i]; wp.g[i] = lng[i]; wp.bb[i] = lnb[i]; }
    k_wb<<<480, 512>>>(wp);

    PPtr pa;
    for (int i = 0; i < 4; i++) pa.p[i] = pooled[i];
    cudaFuncSetAttribute(k_main, cudaFuncAttributeMaxDynamicSharedMemorySize, SM_TOTAL);
    k_main<<<512, 512, SM_TOTAL>>>(pa);
    k_fin<<<256, 256>>>(ls, (float*)d_out);
}

// round 13
// speedup vs baseline: 1.2678x; 1.1551x over previous
#include <cuda_runtime.h>
#include <cuda_bf16.h>
#include <cstdint>
#include <cstring>

#define DI __device__ __forceinline__

// ---------------- static scratch (no allocation allowed) ----------------
__device__ __align__(16) __nv_bfloat16 g_sW[1966080];      // g1*W1 bf16 [C][512] per level
__device__ float g_proto_mean[4 * 2048];
__device__ float g_s2ss2[8];                               // per level: sum, sumsq of proto ctx
__device__ float g_gw[2048], g_bw[2048], g_u2[2048];
__device__ float g_text[4096];                             // l2-normalized text [8][512]
__device__ float g_pss[2][32768];                          // [half][lvl*8192+b] ||h||^2 partial
__device__ float g_pdk[2][262144];                         // [half][(lvl*8192+b)*8+k] dot partial

__constant__ int cC[4]  = {256, 512, 1024, 2048};
__constant__ int cWO[4] = {0, 131072, 393216, 917504};     // elem offsets into g_sW

// ---------------- PTX helpers ----------------
DI uint32_t su32(const void* p) {
    uint32_t a;
    asm("{ .reg .u64 t; cvta.to.shared.u64 t, %1; cvt.u32.u64 %0, t; }" : "=r"(a) : "l"(p));
    return a;
}
DI void cp16(uint32_t d, const void* s) {
    asm volatile("cp.async.cg.shared.global [%0], [%1], 16;" :: "r"(d), "l"(s));
}
DI void cpcommit() { asm volatile("cp.async.commit_group;"); }
DI void sts128(uint32_t a, uint32_t r0, uint32_t r1, uint32_t r2, uint32_t r3) {
    asm volatile("st.shared.v4.b32 [%0], {%1, %2, %3, %4};"
                 :: "r"(a), "r"(r0), "r"(r1), "r"(r2), "r"(r3) : "memory");
}
DI void ldmA(uint32_t* r, uint32_t a) {
    asm volatile("ldmatrix.sync.aligned.m8n8.x4.shared.b16 {%0,%1,%2,%3}, [%4];"
                 : "=r"(r[0]), "=r"(r[1]), "=r"(r[2]), "=r"(r[3]) : "r"(a));
}
DI void ldmBT(uint32_t* r, uint32_t a) {
    asm volatile("ldmatrix.sync.aligned.m8n8.x4.trans.shared.b16 {%0,%1,%2,%3}, [%4];"
                 : "=r"(r[0]), "=r"(r[1]), "=r"(r[2]), "=r"(r[3]) : "r"(a));
}
DI void mma16816(float* c, const uint32_t* a, const uint32_t* b) {
    asm volatile(
        "mma.sync.aligned.m16n8k16.row.col.f32.bf16.bf16.f32 "
        "{%0,%1,%2,%3}, {%4,%5,%6,%7}, {%8,%9}, {%0,%1,%2,%3};"
        : "+f"(c[0]), "+f"(c[1]), "+f"(c[2]), "+f"(c[3])
        : "r"(a[0]), "r"(a[1]), "r"(a[2]), "r"(a[3]), "r"(b[0]), "r"(b[1]));
}

// ---------------- fused precompute: proto mean + text l2norm + accum zero ----------------
struct PrePtr {
    const float* proto[4];
    const float* bias[4];
    const float* text;
};

__global__ void k_pre(PrePtr P) {
    const int bx = blockIdx.x;
    if (bx < 15) {
        const int lvl = bx < 1 ? 0 : bx < 3 ? 1 : bx < 7 ? 2 : 3;
        const int base4[4] = {0, 1, 3, 7};
        const int C = cC[lvl];
        const int c = (bx - base4[lvl]) * 256 + threadIdx.x;
        const float* Pp = P.proto[lvl];
        float s = 0.f;
        #pragma unroll 8
        for (int p = 0; p < 64; p++) s += Pp[p * C + c];
        const float pm = s * 0.015625f;
        g_proto_mean[lvl * 2048 + c] = pm;
        __shared__ float r1[256], r2[256];
        r1[threadIdx.x] = pm; r2[threadIdx.x] = pm * pm; __syncthreads();
        for (int o = 128; o; o >>= 1) {
            if (threadIdx.x < o) { r1[threadIdx.x] += r1[threadIdx.x + o]; r2[threadIdx.x] += r2[threadIdx.x + o]; }
            __syncthreads();
        }
        if (!threadIdx.x) {
            atomicAdd(&g_s2ss2[lvl * 2], r1[0]);
            atomicAdd(&g_s2ss2[lvl * 2 + 1], r2[0]);
        }
    } else if (bx == 15) {
        const int w = threadIdx.x >> 5, ln = threadIdx.x & 31;
        float4 v[4]; float ss = 0.f;
        #pragma unroll
        for (int j = 0; j < 4; j++) {
            v[j] = *(const float4*)(P.text + w * 512 + ln * 4 + j * 128);
            ss += v[j].x * v[j].x + v[j].y * v[j].y + v[j].z * v[j].z + v[j].w * v[j].w;
        }
        #pragma unroll
        for (int o = 16; o; o >>= 1) ss += __shfl_xor_sync(~0u, ss, o);
        const float inv = 1.f / fmaxf(sqrtf(ss), 1e-12f);
        #pragma unroll
        for (int j = 0; j < 4; j++) {
            float4 u = v[j]; u.x *= inv; u.y *= inv; u.z *= inv; u.w *= inv;
            *(float4*)(g_text + w * 512 + ln * 4 + j * 128) = u;
        }
    } else {
        const int lvl = bx - 16;
        #pragma unroll
        for (int i = 0; i < 2; i++) {
            const int d = threadIdx.x + i * 256;
            g_gw[lvl * 512 + d] = 0.f;
            g_u2[lvl * 512 + d] = 0.f;
            g_bw[lvl * 512 + d] = P.bias[lvl][d];
        }
        if (lvl == 0 && threadIdx.x < 8) g_s2ss2[threadIdx.x] = 0.f;
    }
}

struct WPtr { const float* W[4]; const float* g[4]; const float* bb[4]; };

// 480 blocks x 512 threads; block = 16 j-rows, thread = 4 rows x 4 cols (float4 loads).
__global__ void k_wb(WPtr P) {
    __shared__ float red[3 * 128 * 12];
    const int cb = blockIdx.x;
    const int lvl = cb < 32 ? 0 : cb < 96 ? 1 : cb < 224 ? 2 : 3;
    const int base4[4] = {0, 32, 96, 224};
    const int j0 = (cb - base4[lvl]) * 16;
    const int C = cC[lvl];
    const int grp = threadIdx.x >> 7;
    const int ci = threadIdx.x & 127;
    const int c0 = ci * 4;
    const int jb = j0 + grp * 4;
    const float* W = P.W[lvl];
    const float* gg = P.g[lvl];
    const float* bv = P.bb[lvl];
    float gw[4] = {0, 0, 0, 0}, bw[4] = {0, 0, 0, 0}, uu[4] = {0, 0, 0, 0};
    uint2 outw[4];
    #pragma unroll
    for (int jj = 0; jj < 4; jj++) {
        const int j = jb + jj;
        const float gj = gg[j], bj = bv[j];
        const float4 w4 = *(const float4*)(W + (size_t)j * 512 + c0);
        gw[0] = fmaf(gj, w4.x, gw[0]); gw[1] = fmaf(gj, w4.y, gw[1]);
        gw[2] = fmaf(gj, w4.z, gw[2]); gw[3] = fmaf(gj, w4.w, gw[3]);
        bw[0] = fmaf(bj, w4.x, bw[0]); bw[1] = fmaf(bj, w4.y, bw[1]);
        bw[2] = fmaf(bj, w4.z, bw[2]); bw[3] = fmaf(bj, w4.w, bw[3]);
        if (j0 >= C) {
            const float pj = g_proto_mean[lvl * 2048 + (j - C)] * gj;
            uu[0] = fmaf(pj, w4.x, uu[0]); uu[1] = fmaf(pj, w4.y, uu[1]);
            uu[2] = fmaf(pj, w4.z, uu[2]); uu[3] = fmaf(pj, w4.w, uu[3]);
        } else {
            __nv_bfloat162 h0 = __floats2bfloat162_rn(gj * w4.x, gj * w4.y);
            __nv_bfloat162 h1 = __floats2bfloat162_rn(gj * w4.z, gj * w4.w);
            memcpy(&outw[jj].x, &h0, 4);
            memcpy(&outw[jj].y, &h1, 4);
        }
    }
    if (j0 < C) {
        #pragma unroll
        for (int jj = 0; jj < 4; jj++)
            *(uint2*)(g_sW + cWO[lvl] + (size_t)(jb + jj) * 512 + c0) = outw[jj];
    }
    if (grp) {
        float* r = red + ((grp - 1) * 128 + ci) * 12;
        #pragma unroll
        for (int c = 0; c < 4; c++) { r[c] = gw[c]; r[4 + c] = bw[c]; r[8 + c] = uu[c]; }
    }
    __syncthreads();
    if (!grp) {
        #pragma unroll
        for (int g2 = 0; g2 < 3; g2++) {
            const float* r = red + (g2 * 128 + ci) * 12;
            #pragma unroll
            for (int c = 0; c < 4; c++) { gw[c] += r[c]; bw[c] += r[4 + c]; uu[c] += r[8 + c]; }
        }
        #pragma unroll
        for (int c = 0; c < 4; c++) {
            atomicAdd(&g_gw[lvl * 512 + c0 + c], gw[c]);
            atomicAdd(&g_bw[lvl * 512 + c0 + c], bw[c]);
        }
        if (j0 >= C) {
            #pragma unroll
            for (int c = 0; c < 4; c++) atomicAdd(&g_u2[lvl * 512 + c0 + c], uu[c]);
        }
    }
}

// ---------------- main fused GEMM + epilogue ----------------
// CTA: 64 rows x 256 cols (N-split half), 256 threads, 8 warps (warp = 32 cols).
// 2 CTAs/SM co-resident. A: fp32 LDG -> bf16 STS, 2 x 8KB. B: 4-stage ring, 4 x 16KB.
static constexpr int SM_B = 16384;
static constexpr int SM_TOTAL = 16384 + 4 * 16384;   // 81920 B per CTA

struct PPtr { const float* p[4]; };

__global__ void __launch_bounds__(256, 2) k_main(PPtr PA) {
    extern __shared__ char smem[];
    const uint32_t sb = su32(smem);
    const int tid = threadIdx.x, wid = tid >> 5, lane = tid & 31;
    const int bx = blockIdx.x;
    const int lvl = 3 - (bx >> 8);              // big levels first
    const int idx = bx & 255;
    const int tile = idx >> 1, half = idx & 1;
    const int C = cC[lvl];
    const int nch = C >> 5;
    const int row0 = tile * 64;
    const float* Ag = PA.p[lvl] + (size_t)row0 * C;
    const __nv_bfloat16* Bg = g_sW + cWO[lvl] + half * 256;

    // A: thread t -> row t>>2, floats [(t&3)*8, +8) of each 32-wide chunk
    const int arow = tid >> 2, acolf = (tid & 3) * 8;
    const float* aSrc = Ag + (size_t)arow * C + acolf;
    const uint32_t aDst = sb + arow * 128 + ((acolf * 2) ^ ((arow & 7) << 4));

    float acc[4][4][4];
    #pragma unroll
    for (int i = 0; i < 4; i++)
        #pragma unroll
        for (int j = 0; j < 4; j++)
            #pragma unroll
            for (int k = 0; k < 4; k++) acc[i][j][k] = 0.f;

    const int rbase = (lane & 7) + 8 * ((lane >> 3) & 1);
    const int cbmat = (lane >> 4) * 16;
    const int xorv = (rbase & 7) << 4;
    const int cb = wid * 32;                    // warp col base within the 256-half

    auto issueB = [&](int ch) {
        const int st = ch & 3;
        const __nv_bfloat16* bp = Bg + (size_t)(ch * 32) * 512;
        #pragma unroll
        for (int i = 0; i < 4; i++) {
            const int c = tid + 256 * i, r = c >> 5, c16 = c & 31;
            cp16(sb + SM_B + st * 16384 + r * 512 + ((c16 * 16) ^ ((r & 7) << 4)),
                 bp + (size_t)r * 512 + c16 * 8);
        }
        cpcommit();
    };

    float rs = 0.f, rq = 0.f;       // per-thread partial row stats
    float4 av0 = *(const float4*)(aSrc);
    float4 av1 = *(const float4*)(aSrc + 4);
    issueB(0);
    if (nch > 1) issueB(1);
    if (nch > 2) issueB(2);

    for (int ch = 0; ch < nch; ch++) {
        if (ch + 2 < nch)      asm volatile("cp.async.wait_group 2;");
        else if (ch + 1 < nch) asm volatile("cp.async.wait_group 1;");
        else                   asm volatile("cp.async.wait_group 0;");
        // convert + STS A(ch) from regs, accumulate stats
        {
            rs += av0.x + av0.y + av0.z + av0.w + av1.x + av1.y + av1.z + av1.w;
            rq = fmaf(av0.x, av0.x, rq); rq = fmaf(av0.y, av0.y, rq);
            rq = fmaf(av0.z, av0.z, rq); rq = fmaf(av0.w, av0.w, rq);
            rq = fmaf(av1.x, av1.x, rq); rq = fmaf(av1.y, av1.y, rq);
            rq = fmaf(av1.z, av1.z, rq); rq = fmaf(av1.w, av1.w, rq);
            __nv_bfloat162 h0 = __floats2bfloat162_rn(av0.x, av0.y);
            __nv_bfloat162 h1 = __floats2bfloat162_rn(av0.z, av0.w);
            __nv_bfloat162 h2 = __floats2bfloat162_rn(av1.x, av1.y);
            __nv_bfloat162 h3 = __floats2bfloat162_rn(av1.z, av1.w);
            uint32_t q0, q1, q2, q3;
            memcpy(&q0, &h0, 4); memcpy(&q1, &h1, 4);
            memcpy(&q2, &h2, 4); memcpy(&q3, &h3, 4);
            sts128(aDst + (ch & 1) * 8192, q0, q1, q2, q3);
        }
        __syncthreads();            // the ONLY barrier per chunk
        if (ch + 3 < nch) issueB(ch + 3);
        if (ch + 1 < nch) {
            av0 = *(const float4*)(aSrc + (ch + 1) * 32);
            av1 = *(const float4*)(aSrc + (ch + 1) * 32 + 4);
        }
        const uint32_t sA = sb + (ch & 1) * 8192;
        const uint32_t sB = sb + SM_B + (ch & 3) * 16384;
        #pragma unroll
        for (int ks = 0; ks < 2; ks++) {
            uint32_t bf[2][4], af[4][4];
            #pragma unroll
            for (int np = 0; np < 2; np++)
                ldmBT(bf[np], sB + (ks * 16 + rbase) * 512 +
                              ((((cb + np * 16) * 2) + cbmat) ^ xorv));
            #pragma unroll
            for (int mt = 0; mt < 4; mt++)
                ldmA(af[mt], sA + (mt * 16 + rbase) * 128 + (((ks * 16) * 2 + cbmat) ^ xorv));
            #pragma unroll
            for (int mt = 0; mt < 4; mt++)
                #pragma unroll
                for (int nt = 0; nt < 4; nt++)
                    mma16816(acc[mt][nt], af[mt], &bf[nt >> 1][(nt & 1) * 2]);
        }
    }
    __syncthreads();                // mainloop smem reads done before epilogue reuse

    // -------- epilogue (register-resident; half-tile partials to gmem) --------
    float* sf   = (float*)smem;
    float* txs  = sf;                 // [8][256] this half
    float* u2s  = sf + 2048;
    float* gws  = u2s + 256;
    float* bws  = gws + 256;
    float2* srs = (float2*)(bws + 256);       // [64] (mean, inv)
    float2* sraw = srs + 64;                  // [64] raw (sum, sumsq)
    float* prp  = (float*)(sraw + 64);        // [64 rows][8 warps][9]

    // reduce row stats across the 4 threads of each row (lanes differ in bits 0-1)
    #pragma unroll
    for (int o = 1; o < 4; o <<= 1) {
        rs += __shfl_xor_sync(~0u, rs, o);
        rq += __shfl_xor_sync(~0u, rq, o);
    }
    if ((tid & 3) == 0) sraw[arow] = make_float2(rs, rq);

    #pragma unroll
    for (int i = 0; i < 8; i++) {
        const int e = tid + 256 * i;
        txs[e] = g_text[(e >> 8) * 512 + half * 256 + (e & 255)];
    }
    u2s[tid] = g_u2[lvl * 512 + half * 256 + tid];
    gws[tid] = g_gw[lvl * 512 + half * 256 + tid];
    bws[tid] = g_bw[lvl * 512 + half * 256 + tid];
    __syncthreads();
    if (tid < 64) {
        const float s = sraw[tid].x + g_s2ss2[lvl * 2];
        const float q = sraw[tid].y + g_s2ss2[lvl * 2 + 1];
        const float invN = 1.f / (float)(2 * C);
        const float m = s * invN;
        const float var = q * invN - m * m;
        srs[tid] = make_float2(m, rsqrtf(var + 1e-5f));
    }
    __syncthreads();

    const int rr0 = lane >> 2;
    const int cq = (lane & 3) * 2;
    #pragma unroll
    for (int mt = 0; mt < 4; mt++) {
        const int r0 = mt * 16 + rr0, r1 = r0 + 8;
        const float2 s0 = srs[r0], s1 = srs[r1];
        float ss0 = 0.f, ss1 = 0.f;
        float dk0[8] = {0,0,0,0,0,0,0,0}, dk1[8] = {0,0,0,0,0,0,0,0};
        #pragma unroll
        for (int nt = 0; nt < 4; nt++) {
            const int c = cb + nt * 8 + cq;
            const float u2a = u2s[c], u2b = u2s[c + 1];
            const float gwa = gws[c], gwb = gws[c + 1];
            const float bwa = bws[c], bwb = bws[c + 1];
            const float h0 = fmaxf(s0.y * (acc[mt][nt][0] + u2a - s0.x * gwa) + bwa, 0.f);
            const float h1 = fmaxf(s0.y * (acc[mt][nt][1] + u2b - s0.x * gwb) + bwb, 0.f);
            const float h2 = fmaxf(s1.y * (acc[mt][nt][2] + u2a - s1.x * gwa) + bwa, 0.f);
            const float h3 = fmaxf(s1.y * (acc[mt][nt][3] + u2b - s1.x * gwb) + bwb, 0.f);
            ss0 = fmaf(h0, h0, ss0); ss0 = fmaf(h1, h1, ss0);
            ss1 = fmaf(h2, h2, ss1); ss1 = fmaf(h3, h3, ss1);
            #pragma unroll
            for (int k = 0; k < 8; k++) {
                const float2 t2 = *(const float2*)(txs + k * 256 + c);
                dk0[k] = fmaf(h0, t2.x, dk0[k]); dk0[k] = fmaf(h1, t2.y, dk0[k]);
                dk1[k] = fmaf(h2, t2.x, dk1[k]); dk1[k] = fmaf(h3, t2.y, dk1[k]);
            }
        }
        #pragma unroll
        for (int o = 1; o < 4; o <<= 1) {
            ss0 += __shfl_xor_sync(~0u, ss0, o);
            ss1 += __shfl_xor_sync(~0u, ss1, o);
            #pragma unroll
            for (int k = 0; k < 8; k++) {
                dk0[k] += __shfl_xor_sync(~0u, dk0[k], o);
                dk1[k] += __shfl_xor_sync(~0u, dk1[k], o);
            }
        }
        if ((lane & 3) == 0) {
            float* p0 = prp + (r0 * 8 + wid) * 9;
            float* p1 = prp + (r1 * 8 + wid) * 9;
            p0[0] = ss0; p1[0] = ss1;
            #pragma unroll
            for (int k = 0; k < 8; k++) { p0[1 + k] = dk0[k]; p1[1 + k] = dk1[k]; }
        }
    }
    __syncthreads();
    if (tid < 64) {
        float ss = 0.f;
        #pragma unroll
        for (int w = 0; w < 8; w++) ss += prp[(tid * 8 + w) * 9];
        g_pss[half][(lvl << 13) + row0 + tid] = ss;
    }
    #pragma unroll
    for (int it = 0; it < 2; it++) {
        const int e = tid + 256 * it;
        const int row = e >> 3, k = e & 7;
        float d = 0.f;
        #pragma unroll
        for (int w = 0; w < 8; w++) d += prp[(row * 8 + w) * 9 + 1 + k];
        g_pdk[half][(size_t)((lvl << 13) + row0 + row) * 8 + k] = d;
    }
}

// ---------------- final combine: halves merge + l2norm scale + softmax ----------------
__global__ void k_fin(const float* __restrict__ ls, float* __restrict__ out) {
    const int i = blockIdx.x * 256 + threadIdx.x;  // b*8 + k
    const float s = fmaxf(ls[0], 1e-4f) * 0.044194173824159216f;  // clip * 1/sqrt(512)
    const int b = i >> 3, k = i & 7;
    float z[4], mx = -1e30f;
    #pragma unroll
    for (int l = 0; l < 4; l++) {
        const int idx = (l << 13) + b;
        const float ss = g_pss[0][idx] + g_pss[1][idx];
        const float d  = g_pdk[0][(size_t)idx * 8 + k] + g_pdk[1][(size_t)idx * 8 + k];
        z[l] = d / fmaxf(sqrtf(ss), 1e-12f) * s;
        mx = fmaxf(mx, z[l]);
    }
    float e[4], sum = 0.f;
    #pragma unroll
    for (int l = 0; l < 4; l++) { e[l] = expf(z[l] - mx); sum += e[l]; }
    const float inv = 1.f / sum;
    #pragma unroll
    for (int l = 0; l < 4; l++) out[i * 4 + l] = e[l] * inv;
}

// ---------------- launch ----------------
extern "C" void kernel_launch(void* const* d_in, const int* in_sizes, int n_in,
                              void* d_out, int out_size) {
    const float *pooled[4], *proto[4], *lng[4], *lnb[4], *W[4], *bias[4];
    const bool interleaved = (in_sizes[1] == 16384);  // proto_0 = 64*256
    for (int i = 0; i < 4; i++) {
        if (interleaved) {
            pooled[i] = (const float*)d_in[6 * i + 0];
            proto[i]  = (const float*)d_in[6 * i + 1];
            lng[i]    = (const float*)d_in[6 * i + 2];
            lnb[i]    = (const float*)d_in[6 * i + 3];
            W[i]      = (const float*)d_in[6 * i + 4];
            bias[i]   = (const float*)d_in[6 * i + 5];
        } else {
            pooled[i] = (const float*)d_in[i];
            proto[i]  = (const float*)d_in[4 + i];
            lng[i]    = (const float*)d_in[8 + i];
            lnb[i]    = (const float*)d_in[12 + i];
            W[i]      = (const float*)d_in[16 + i];
            bias[i]   = (const float*)d_in[20 + i];
        }
    }
    const float* text = (const float*)d_in[24];
    const float* ls   = (const float*)d_in[25];

    PrePtr pr;
    for (int i = 0; i < 4; i++) { pr.proto[i] = proto[i]; pr.bias[i] = bias[i]; }
    pr.text = text;
    k_pre<<<20, 256>>>(pr);

    WPtr wp;
    for (int i = 0; i < 4; i++) { wp.W[i] = W[i]; wp.g[i] = lng[i]; wp.bb[i] = lnb[i]; }
    k_wb<<<480, 512>>>(wp);

    PPtr pa;
    for (int i = 0; i < 4; i++) pa.p[i] = pooled[i];
    cudaFuncSetAttribute(k_main, cudaFuncAttributeMaxDynamicSharedMemorySize, SM_TOTAL);
    k_main<<<1024, 256, SM_TOTAL>>>(pa);
    k_fin<<<256, 256>>>(ls, (float*)d_out);
}